// round 14
// baseline (speedup 1.0000x reference)
#include <cuda_runtime.h>
#include <cstdint>

#define DIM     128
#define MAXN    65536
#define BSTRIDE 64     // fixed bucket stride; Poisson(12.8) max degree << 64

// Scratch (no allocations allowed). g_cnt is zero at module load; the
// aggregate kernel resets it each run so graph replays see a clean state.
__device__ float g_ssrc[MAXN];                        // src logit half
__device__ float g_sdst[MAXN];                        // dst logit half + bias
__device__ int   g_cnt[MAXN];                         // per-dst bucket fill count
__device__ int   g_bucket[(size_t)MAXN * BSTRIDE];    // src ids, strided buckets

// ---------------------------------------------------------------------------
// Kernel 1 (fused, warp-striped): 224-thread blocks (7 warps).
//   warps 0-1: bucket-append (atomic cursor + strided write) — latency bound.
//   warps 2-6: precompute node logit halves — DRAM-stream bound.
// No prefix scan needed anywhere: fixed-stride buckets replace the CSR build.
__global__ void append_precompute_kernel(const int* __restrict__ edge_index,
                                         const float* __restrict__ src_feat,
                                         const float* __restrict__ dst_feat,
                                         const float* __restrict__ att_w,
                                         const float* __restrict__ att_b,
                                         int n_edges, int n_src, int n_dst) {
    int wid = threadIdx.x >> 5;
    int lane = threadIdx.x & 31;

    if (wid < 2) {
        // ---- bucket append: 1 edge per thread
        int gw = blockIdx.x * 2 + wid;
        int e = gw * 32 + lane;
        if (e < n_edges) {
            int s = edge_index[e];
            int d = edge_index[n_edges + e];
            int pos = atomicAdd(&g_cnt[d], 1);
            if (pos < BSTRIDE)
                g_bucket[(size_t)d * BSTRIDE + pos] = s;
        }
    } else {
        // ---- precompute: 1 node row per warp
        int row = blockIdx.x * 5 + (wid - 2);
        int nmax = n_src > n_dst ? n_src : n_dst;
        if (row >= nmax) return;

        float4 w1 = ((const float4*)att_w)[lane];        // W[0:128]
        float4 w2 = ((const float4*)att_w)[32 + lane];   // W[128:256]

        float acc1 = 0.f, acc2 = 0.f;
        if (row < n_src) {
            float4 a = ((const float4*)(src_feat + (size_t)row * DIM))[lane];
            acc1 = a.x * w1.x + a.y * w1.y + a.z * w1.z + a.w * w1.w;
        }
        if (row < n_dst) {
            float4 b = ((const float4*)(dst_feat + (size_t)row * DIM))[lane];
            acc2 = b.x * w2.x + b.y * w2.y + b.z * w2.z + b.w * w2.w;
        }
        #pragma unroll
        for (int off = 16; off; off >>= 1) {
            acc1 += __shfl_xor_sync(0xffffffffu, acc1, off);
            acc2 += __shfl_xor_sync(0xffffffffu, acc2, off);
        }
        if (lane == 0) {
            if (row < n_src) g_ssrc[row] = acc1;
            if (row < n_dst) g_sdst[row] = acc2 + att_b[0];
        }
    }
}

// ---------------------------------------------------------------------------
// Kernel 2: one warp per dst row. Reads its bucket (deg from g_cnt, then
// resets g_cnt for the next replay), register accumulation, fused normalize,
// single write. 2-way manual MLP on the gathers.
__global__ void aggregate_kernel(const float* __restrict__ src_feat,
                                 float* __restrict__ out, int n_dst) {
    int warp = (blockIdx.x * blockDim.x + threadIdx.x) >> 5;
    int lane = threadIdx.x & 31;
    if (warp >= n_dst) return;

    int deg = g_cnt[warp];                    // warp-broadcast load
    if (lane == 0) g_cnt[warp] = 0;           // reset invariant (after all reads)
    if (deg > BSTRIDE) deg = BSTRIDE;

    const int* bucket = g_bucket + (size_t)warp * BSTRIDE;
    float sd = g_sdst[warp];

    float4 acc = make_float4(0.f, 0.f, 0.f, 0.f);
    float csum = 0.f;

    int i = 0;
    for (; i + 2 <= deg; i += 2) {
        int s0 = bucket[i];
        int s1 = bucket[i + 1];
        float a0 = 1.f / (1.f + __expf(-(g_ssrc[s0] + sd)));
        float a1 = 1.f / (1.f + __expf(-(g_ssrc[s1] + sd)));
        float4 v0 = ((const float4*)(src_feat + (size_t)s0 * DIM))[lane];
        float4 v1 = ((const float4*)(src_feat + (size_t)s1 * DIM))[lane];
        acc.x += a0 * v0.x + a1 * v1.x;
        acc.y += a0 * v0.y + a1 * v1.y;
        acc.z += a0 * v0.z + a1 * v1.z;
        acc.w += a0 * v0.w + a1 * v1.w;
        csum += a0 + a1;
    }
    if (i < deg) {
        int s0 = bucket[i];
        float a0 = 1.f / (1.f + __expf(-(g_ssrc[s0] + sd)));
        float4 v0 = ((const float4*)(src_feat + (size_t)s0 * DIM))[lane];
        acc.x += a0 * v0.x; acc.y += a0 * v0.y;
        acc.z += a0 * v0.z; acc.w += a0 * v0.w;
        csum += a0;
    }

    float inv = 1.f / fmaxf(csum, 1e-8f);
    ((float4*)(out + (size_t)warp * DIM))[lane] =
        make_float4(acc.x * inv, acc.y * inv, acc.z * inv, acc.w * inv);
}

// ---------------------------------------------------------------------------
extern "C" void kernel_launch(void* const* d_in, const int* in_sizes, int n_in,
                              void* d_out, int out_size) {
    const float* src_feat = (const float*)d_in[0];
    const float* dst_feat = (const float*)d_in[1];
    const float* att_w    = (const float*)d_in[2];
    const float* att_b    = (const float*)d_in[3];
    const int*   edge_idx = (const int*)d_in[4];   // int32 (JAX x64 disabled)

    int n_src   = in_sizes[0] / DIM;
    int n_dst   = out_size / DIM;
    int n_edges = in_sizes[4] / 2;
    float* out  = (float*)d_out;

    int nmax = n_src > n_dst ? n_src : n_dst;

    // Kernel 1: bucket append (2 warps/blk) + precompute (5 warps/blk)
    {
        int sw = (n_edges + 31) / 32;          // append warps
        int b1 = (sw + 1) / 2;
        int b2 = (nmax + 4) / 5;
        int blocks = b1 > b2 ? b1 : b2;
        append_precompute_kernel<<<blocks, 224>>>(edge_idx, src_feat, dst_feat,
                                                  att_w, att_b,
                                                  n_edges, n_src, n_dst);
    }
    // Kernel 2: aggregate
    aggregate_kernel<<<(n_dst * 32 + 255) / 256, 256>>>(src_feat, out, n_dst);
}

// round 15
// speedup vs baseline: 2.2762x; 2.2762x over previous
#include <cuda_runtime.h>
#include <cstdint>

#define DIM  128
#define MAXN 65536
#define MAXE (1 << 20)
#define NB_MAX (MAXN / 1024 + 1)

// Scratch (no allocations allowed). Zero-initialized at module load; every
// run re-zeroes g_cnt in scan_local_kernel so replays see a clean histogram.
__device__ float g_ssrc[MAXN];          // src logit half
__device__ float g_sdst[MAXN];          // dst logit half + bias
__device__ int   g_cnt[MAXN];           // per-dst degree histogram
__device__ int   g_start[MAXN + 1];     // CSR row offsets, LOCAL-exclusive (+ sentinel)
__device__ int   g_cursor[MAXN];        // scatter cursors, LOCAL-exclusive
__device__ int   g_bsum[NB_MAX];        // per-1024-block global base offsets
__device__ int   g_ssorted[MAXE];       // src ids bucketed by dst

// ---------------------------------------------------------------------------
// Kernel 1: degree histogram over dst. 4 edges/thread, int4 loads.
__global__ void hist_kernel(const int* __restrict__ edge_index, int n_edges) {
    int t = blockIdx.x * blockDim.x + threadIdx.x;
    int base = t * 4;
    const int* dst_row = edge_index + n_edges;
    if (base + 4 <= n_edges) {
        int4 d = ((const int4*)dst_row)[t];
        atomicAdd(&g_cnt[d.x], 1);
        atomicAdd(&g_cnt[d.y], 1);
        atomicAdd(&g_cnt[d.z], 1);
        atomicAdd(&g_cnt[d.w], 1);
    } else {
        for (int e = base; e < n_edges; e++)
            atomicAdd(&g_cnt[dst_row[e]], 1);
    }
}

// ---------------------------------------------------------------------------
// Kernel 2: per-block exclusive scan of g_cnt (1024 elems/block). Coalesced.
// Writes LOCAL-exclusive offsets into both g_start and g_cursor (consumers
// add g_bsum[i>>10] themselves). Re-zeroes g_cnt for the next graph replay.
__global__ void scan_local_kernel(int n) {
    int i = blockIdx.x * 1024 + threadIdx.x;
    int lane = threadIdx.x & 31, wid = threadIdx.x >> 5;
    int v = 0;
    if (i < n) {
        v = g_cnt[i];
        g_cnt[i] = 0;                       // reset invariant for next run
    }

    int x = v;
    #pragma unroll
    for (int o = 1; o < 32; o <<= 1) {
        int y = __shfl_up_sync(0xffffffffu, x, o);
        if (lane >= o) x += y;
    }
    __shared__ int wsum[32];
    if (lane == 31) wsum[wid] = x;
    __syncthreads();
    if (wid == 0) {
        int w = wsum[lane];
        #pragma unroll
        for (int o = 1; o < 32; o <<= 1) {
            int y = __shfl_up_sync(0xffffffffu, w, o);
            if (lane >= o) w += y;
        }
        wsum[lane] = w;
    }
    __syncthreads();
    int base = wid ? wsum[wid - 1] : 0;
    int incl = x + base;
    int excl = incl - v;                     // local exclusive
    if (i <= n) g_start[i] = excl;
    if (i < n)  g_cursor[i] = excl;
    if (threadIdx.x == 1023) g_bsum[blockIdx.x] = incl;
}

// Kernel 3: exclusive scan of block sums — one warp, shfl-based.
__global__ void scan_bsum_kernel(int nb) {
    int lane = threadIdx.x;                  // blockDim.x == 32
    int i0 = 2 * lane, i1 = 2 * lane + 1;
    int e0 = (i0 < nb) ? g_bsum[i0] : 0;
    int e1 = (i1 < nb) ? g_bsum[i1] : 0;
    int s = e0 + e1;

    int x = s;
    #pragma unroll
    for (int o = 1; o < 32; o <<= 1) {
        int y = __shfl_up_sync(0xffffffffu, x, o);
        if (lane >= o) x += y;
    }
    int ex = x - s;                          // exclusive prefix of pair sums
    if (i0 < nb) g_bsum[i0] = ex;
    if (i1 < nb) g_bsum[i1] = ex + e0;
}

// ---------------------------------------------------------------------------
// Kernel 4 (fused, warp-striped): 224-thread blocks (7 warps).
//   warps 0-1: scatter (bucket src ids by dst) — atomic/latency bound.
//   warps 2-6: precompute node logit halves   — DRAM-stream bound.
__global__ void scatter_precompute_kernel(const int* __restrict__ edge_index,
                                          const float* __restrict__ src_feat,
                                          const float* __restrict__ dst_feat,
                                          const float* __restrict__ att_w,
                                          const float* __restrict__ att_b,
                                          int n_edges, int n_src, int n_dst) {
    int wid = threadIdx.x >> 5;
    int lane = threadIdx.x & 31;

    if (wid < 2) {
        // ---- scatter: 1 edge per thread; global pos = local cursor + block base
        int gw = blockIdx.x * 2 + wid;
        int e = gw * 32 + lane;
        if (e < n_edges) {
            int s = edge_index[e];
            int d = edge_index[n_edges + e];
            int pos = atomicAdd(&g_cursor[d], 1) + g_bsum[d >> 10];
            g_ssorted[pos] = s;
        }
    } else {
        // ---- precompute: 1 node row per warp
        int row = blockIdx.x * 5 + (wid - 2);
        int nmax = n_src > n_dst ? n_src : n_dst;
        if (row >= nmax) return;

        float4 w1 = ((const float4*)att_w)[lane];        // W[0:128]
        float4 w2 = ((const float4*)att_w)[32 + lane];   // W[128:256]

        float acc1 = 0.f, acc2 = 0.f;
        if (row < n_src) {
            float4 a = ((const float4*)(src_feat + (size_t)row * DIM))[lane];
            acc1 = a.x * w1.x + a.y * w1.y + a.z * w1.z + a.w * w1.w;
        }
        if (row < n_dst) {
            float4 b = ((const float4*)(dst_feat + (size_t)row * DIM))[lane];
            acc2 = b.x * w2.x + b.y * w2.y + b.z * w2.z + b.w * w2.w;
        }
        #pragma unroll
        for (int off = 16; off; off >>= 1) {
            acc1 += __shfl_xor_sync(0xffffffffu, acc1, off);
            acc2 += __shfl_xor_sync(0xffffffffu, acc2, off);
        }
        if (lane == 0) {
            if (row < n_src) g_ssrc[row] = acc1;
            if (row < n_dst) g_sdst[row] = acc2 + att_b[0];
        }
    }
}

// ---------------------------------------------------------------------------
// Kernel 5: TWO warps per dst row (R14 evidence: aggregate is latency-bound,
// ~42us vs ~28us traffic floor). Each warp handles half the edge list ->
// per-warp dependent chain halves, independent chains double. Partials
// combine via smem. 8 warps/block = 4 rows/block.
__global__ void aggregate_kernel(const float* __restrict__ src_feat,
                                 float* __restrict__ out, int n_dst) {
    __shared__ float4 s_acc[4][32];     // odd-half partial vectors
    __shared__ float  s_cnt[4];         // odd-half partial gate sums

    int wid  = threadIdx.x >> 5;        // 0..7
    int lane = threadIdx.x & 31;
    int pair = wid >> 1;                // row slot within block: 0..3
    int half = wid & 1;                 // 0 = low half, 1 = high half
    int row  = blockIdx.x * 4 + pair;

    float4 acc = make_float4(0.f, 0.f, 0.f, 0.f);
    float csum = 0.f;

    if (row < n_dst) {
        int beg = g_start[row]     + g_bsum[row >> 10];
        int end = g_start[row + 1] + g_bsum[(row + 1) >> 10];
        float sd = g_sdst[row];

        int cnt = end - beg;
        int c0 = (cnt + 1) >> 1;                 // low-half size
        int b = half ? (beg + c0) : beg;
        int e = half ? end : (beg + c0);

        int i = b;
        for (; i + 2 <= e; i += 2) {
            int s0 = g_ssorted[i];
            int s1 = g_ssorted[i + 1];
            float a0 = 1.f / (1.f + __expf(-(g_ssrc[s0] + sd)));
            float a1 = 1.f / (1.f + __expf(-(g_ssrc[s1] + sd)));
            float4 v0 = ((const float4*)(src_feat + (size_t)s0 * DIM))[lane];
            float4 v1 = ((const float4*)(src_feat + (size_t)s1 * DIM))[lane];
            acc.x += a0 * v0.x + a1 * v1.x;
            acc.y += a0 * v0.y + a1 * v1.y;
            acc.z += a0 * v0.z + a1 * v1.z;
            acc.w += a0 * v0.w + a1 * v1.w;
            csum += a0 + a1;
        }
        if (i < e) {
            int s0 = g_ssorted[i];
            float a0 = 1.f / (1.f + __expf(-(g_ssrc[s0] + sd)));
            float4 v0 = ((const float4*)(src_feat + (size_t)s0 * DIM))[lane];
            acc.x += a0 * v0.x; acc.y += a0 * v0.y;
            acc.z += a0 * v0.z; acc.w += a0 * v0.w;
            csum += a0;
        }
    }

    // combine halves: odd warp publishes, even warp reduces + writes.
    if (half == 1) {
        s_acc[pair][lane] = acc;
        if (lane == 0) s_cnt[pair] = csum;   // csum is lane-replicated
    }
    __syncthreads();
    if (half == 0 && row < n_dst) {
        float4 o = s_acc[pair][lane];
        acc.x += o.x; acc.y += o.y; acc.z += o.z; acc.w += o.w;
        csum += s_cnt[pair];
        float inv = 1.f / fmaxf(csum, 1e-8f);
        ((float4*)(out + (size_t)row * DIM))[lane] =
            make_float4(acc.x * inv, acc.y * inv, acc.z * inv, acc.w * inv);
    }
}

// ---------------------------------------------------------------------------
extern "C" void kernel_launch(void* const* d_in, const int* in_sizes, int n_in,
                              void* d_out, int out_size) {
    const float* src_feat = (const float*)d_in[0];
    const float* dst_feat = (const float*)d_in[1];
    const float* att_w    = (const float*)d_in[2];
    const float* att_b    = (const float*)d_in[3];
    const int*   edge_idx = (const int*)d_in[4];   // int32 (JAX x64 disabled)

    int n_src   = in_sizes[0] / DIM;
    int n_dst   = out_size / DIM;
    int n_edges = in_sizes[4] / 2;
    float* out  = (float*)d_out;

    int nmax = n_src > n_dst ? n_src : n_dst;
    int nb = (n_dst + 1023) / 1024;

    // Kernel 1: histogram
    {
        int t = (n_edges + 3) / 4;
        hist_kernel<<<(t + 255) / 256, 256>>>(edge_idx, n_edges);
    }
    // Kernels 2-3: scan chain
    scan_local_kernel<<<nb, 1024>>>(n_dst);
    scan_bsum_kernel<<<1, 32>>>(nb);
    // Kernel 4: scatter (2 warps/blk) + precompute (5 warps/blk), striped
    {
        int sw = (n_edges + 31) / 32;          // scatter warps
        int nw = nmax;                          // precompute warps
        int b1 = (sw + 1) / 2, b2 = (nw + 4) / 5;
        int blocks = b1 > b2 ? b1 : b2;
        scatter_precompute_kernel<<<blocks, 224>>>(edge_idx, src_feat, dst_feat,
                                                   att_w, att_b,
                                                   n_edges, n_src, n_dst);
    }
    // Kernel 5: aggregate, 2 warps per row, 4 rows per block
    aggregate_kernel<<<(n_dst + 3) / 4, 256>>>(src_feat, out, n_dst);
}

// round 16
// speedup vs baseline: 2.4131x; 1.0602x over previous
#include <cuda_runtime.h>
#include <cstdint>

#define DIM  128
#define MAXN 65536
#define MAXE (1 << 20)
#define NB_MAX (MAXN / 1024 + 1)

// Scratch (no allocations allowed). Zero-initialized at module load; every
// run re-zeroes g_cnt in scan_local_kernel so replays see a clean histogram.
__device__ float g_ssrc[MAXN];          // src logit half
__device__ float g_sdst[MAXN];          // dst logit half + bias
__device__ int   g_cnt[MAXN];           // per-dst degree histogram
__device__ int   g_start[MAXN + 1];     // CSR row offsets, LOCAL-exclusive (+ sentinel)
__device__ int   g_cursor[MAXN];        // scatter cursors, LOCAL-exclusive
__device__ int   g_bsum[NB_MAX];        // per-1024-block global base offsets
__device__ int   g_ssorted[MAXE];       // src ids bucketed by dst

// ---------------------------------------------------------------------------
// Kernel 1: degree histogram over dst. 4 edges/thread, int4 loads.
__global__ void hist_kernel(const int* __restrict__ edge_index, int n_edges) {
    int t = blockIdx.x * blockDim.x + threadIdx.x;
    int base = t * 4;
    const int* dst_row = edge_index + n_edges;
    if (base + 4 <= n_edges) {
        int4 d = ((const int4*)dst_row)[t];
        atomicAdd(&g_cnt[d.x], 1);
        atomicAdd(&g_cnt[d.y], 1);
        atomicAdd(&g_cnt[d.z], 1);
        atomicAdd(&g_cnt[d.w], 1);
    } else {
        for (int e = base; e < n_edges; e++)
            atomicAdd(&g_cnt[dst_row[e]], 1);
    }
}

// ---------------------------------------------------------------------------
// Kernel 2: per-block exclusive scan of g_cnt (1024 elems/block). Coalesced.
// Writes LOCAL-exclusive offsets into both g_start and g_cursor (consumers
// add g_bsum[i>>10] themselves). Re-zeroes g_cnt for the next graph replay.
__global__ void scan_local_kernel(int n) {
    int i = blockIdx.x * 1024 + threadIdx.x;
    int lane = threadIdx.x & 31, wid = threadIdx.x >> 5;
    int v = 0;
    if (i < n) {
        v = g_cnt[i];
        g_cnt[i] = 0;                       // reset invariant for next run
    }

    int x = v;
    #pragma unroll
    for (int o = 1; o < 32; o <<= 1) {
        int y = __shfl_up_sync(0xffffffffu, x, o);
        if (lane >= o) x += y;
    }
    __shared__ int wsum[32];
    if (lane == 31) wsum[wid] = x;
    __syncthreads();
    if (wid == 0) {
        int w = wsum[lane];
        #pragma unroll
        for (int o = 1; o < 32; o <<= 1) {
            int y = __shfl_up_sync(0xffffffffu, w, o);
            if (lane >= o) w += y;
        }
        wsum[lane] = w;
    }
    __syncthreads();
    int base = wid ? wsum[wid - 1] : 0;
    int incl = x + base;
    int excl = incl - v;                     // local exclusive
    if (i <= n) g_start[i] = excl;
    if (i < n)  g_cursor[i] = excl;
    if (threadIdx.x == 1023) g_bsum[blockIdx.x] = incl;
}

// Kernel 3: exclusive scan of block sums — one warp, shfl-based.
__global__ void scan_bsum_kernel(int nb) {
    int lane = threadIdx.x;                  // blockDim.x == 32
    int i0 = 2 * lane, i1 = 2 * lane + 1;
    int e0 = (i0 < nb) ? g_bsum[i0] : 0;
    int e1 = (i1 < nb) ? g_bsum[i1] : 0;
    int s = e0 + e1;

    int x = s;
    #pragma unroll
    for (int o = 1; o < 32; o <<= 1) {
        int y = __shfl_up_sync(0xffffffffu, x, o);
        if (lane >= o) x += y;
    }
    int ex = x - s;                          // exclusive prefix of pair sums
    if (i0 < nb) g_bsum[i0] = ex;
    if (i1 < nb) g_bsum[i1] = ex + e0;
}

// ---------------------------------------------------------------------------
// Kernel 4 (fused, warp-striped, ILP-2): 224-thread blocks (7 warps).
//   warps 0-1: scatter, 2 edges per lane (2 independent atomic chains).
//   warps 2-6: precompute, 2 node rows per warp (4 outstanding row loads,
//              shared shfl-reduction rounds for all 4 accumulators).
// 5000 blocks exactly cover both 640k edges (128/blk) and 50k rows (10/blk).
__global__ void scatter_precompute_kernel(const int* __restrict__ edge_index,
                                          const float* __restrict__ src_feat,
                                          const float* __restrict__ dst_feat,
                                          const float* __restrict__ att_w,
                                          const float* __restrict__ att_b,
                                          int n_edges, int n_src, int n_dst) {
    int wid = threadIdx.x >> 5;
    int lane = threadIdx.x & 31;

    if (wid < 2) {
        // ---- scatter: 2 edges per thread (both coalesced warp loads)
        int gw = blockIdx.x * 2 + wid;
        int e0 = gw * 64 + lane;
        int e1 = e0 + 32;
        int s0 = 0, s1 = 0, d0 = 0, d1 = 0;
        bool v0 = e0 < n_edges, v1 = e1 < n_edges;
        if (v0) { s0 = edge_index[e0]; d0 = edge_index[n_edges + e0]; }
        if (v1) { s1 = edge_index[e1]; d1 = edge_index[n_edges + e1]; }
        int p0 = 0, p1 = 0;
        if (v0) p0 = atomicAdd(&g_cursor[d0], 1) + g_bsum[d0 >> 10];
        if (v1) p1 = atomicAdd(&g_cursor[d1], 1) + g_bsum[d1 >> 10];
        if (v0) g_ssorted[p0] = s0;
        if (v1) g_ssorted[p1] = s1;
    } else {
        // ---- precompute: 2 node rows per warp
        int r0 = blockIdx.x * 10 + (wid - 2) * 2;
        int r1 = r0 + 1;
        int nmax = n_src > n_dst ? n_src : n_dst;
        if (r0 >= nmax) return;

        float4 w1 = ((const float4*)att_w)[lane];        // W[0:128]
        float4 w2 = ((const float4*)att_w)[32 + lane];   // W[128:256]

        float a_s0 = 0.f, a_d0 = 0.f, a_s1 = 0.f, a_d1 = 0.f;
        if (r0 < n_src) {
            float4 a = ((const float4*)(src_feat + (size_t)r0 * DIM))[lane];
            a_s0 = a.x * w1.x + a.y * w1.y + a.z * w1.z + a.w * w1.w;
        }
        if (r1 < n_src) {
            float4 a = ((const float4*)(src_feat + (size_t)r1 * DIM))[lane];
            a_s1 = a.x * w1.x + a.y * w1.y + a.z * w1.z + a.w * w1.w;
        }
        if (r0 < n_dst) {
            float4 b = ((const float4*)(dst_feat + (size_t)r0 * DIM))[lane];
            a_d0 = b.x * w2.x + b.y * w2.y + b.z * w2.z + b.w * w2.w;
        }
        if (r1 < n_dst) {
            float4 b = ((const float4*)(dst_feat + (size_t)r1 * DIM))[lane];
            a_d1 = b.x * w2.x + b.y * w2.y + b.z * w2.z + b.w * w2.w;
        }
        #pragma unroll
        for (int off = 16; off; off >>= 1) {
            a_s0 += __shfl_xor_sync(0xffffffffu, a_s0, off);
            a_d0 += __shfl_xor_sync(0xffffffffu, a_d0, off);
            a_s1 += __shfl_xor_sync(0xffffffffu, a_s1, off);
            a_d1 += __shfl_xor_sync(0xffffffffu, a_d1, off);
        }
        if (lane == 0) {
            float b = att_b[0];
            if (r0 < n_src) g_ssrc[r0] = a_s0;
            if (r1 < n_src) g_ssrc[r1] = a_s1;
            if (r0 < n_dst) g_sdst[r0] = a_d0 + b;
            if (r1 < n_dst) g_sdst[r1] = a_d1 + b;
        }
    }
}

// ---------------------------------------------------------------------------
// Kernel 5: one warp per dst row (R13 form — warp-split measured worse).
// Register accumulation, fused normalize, single write, 2-way MLP.
__global__ void aggregate_kernel(const float* __restrict__ src_feat,
                                 float* __restrict__ out, int n_dst) {
    int warp = (blockIdx.x * blockDim.x + threadIdx.x) >> 5;
    int lane = threadIdx.x & 31;
    if (warp >= n_dst) return;

    int beg = g_start[warp]     + g_bsum[warp >> 10];
    int end = g_start[warp + 1] + g_bsum[(warp + 1) >> 10];
    float sd = g_sdst[warp];

    float4 acc = make_float4(0.f, 0.f, 0.f, 0.f);
    float csum = 0.f;

    int i = beg;
    for (; i + 2 <= end; i += 2) {
        int s0 = g_ssorted[i];
        int s1 = g_ssorted[i + 1];
        float a0 = 1.f / (1.f + __expf(-(g_ssrc[s0] + sd)));
        float a1 = 1.f / (1.f + __expf(-(g_ssrc[s1] + sd)));
        float4 v0 = ((const float4*)(src_feat + (size_t)s0 * DIM))[lane];
        float4 v1 = ((const float4*)(src_feat + (size_t)s1 * DIM))[lane];
        acc.x += a0 * v0.x + a1 * v1.x;
        acc.y += a0 * v0.y + a1 * v1.y;
        acc.z += a0 * v0.z + a1 * v1.z;
        acc.w += a0 * v0.w + a1 * v1.w;
        csum += a0 + a1;
    }
    if (i < end) {
        int s0 = g_ssorted[i];
        float a0 = 1.f / (1.f + __expf(-(g_ssrc[s0] + sd)));
        float4 v0 = ((const float4*)(src_feat + (size_t)s0 * DIM))[lane];
        acc.x += a0 * v0.x; acc.y += a0 * v0.y;
        acc.z += a0 * v0.z; acc.w += a0 * v0.w;
        csum += a0;
    }

    float inv = 1.f / fmaxf(csum, 1e-8f);
    ((float4*)(out + (size_t)warp * DIM))[lane] =
        make_float4(acc.x * inv, acc.y * inv, acc.z * inv, acc.w * inv);
}

// ---------------------------------------------------------------------------
extern "C" void kernel_launch(void* const* d_in, const int* in_sizes, int n_in,
                              void* d_out, int out_size) {
    const float* src_feat = (const float*)d_in[0];
    const float* dst_feat = (const float*)d_in[1];
    const float* att_w    = (const float*)d_in[2];
    const float* att_b    = (const float*)d_in[3];
    const int*   edge_idx = (const int*)d_in[4];   // int32 (JAX x64 disabled)

    int n_src   = in_sizes[0] / DIM;
    int n_dst   = out_size / DIM;
    int n_edges = in_sizes[4] / 2;
    float* out  = (float*)d_out;

    int nmax = n_src > n_dst ? n_src : n_dst;
    int nb = (n_dst + 1023) / 1024;

    // Kernel 1: histogram
    {
        int t = (n_edges + 3) / 4;
        hist_kernel<<<(t + 255) / 256, 256>>>(edge_idx, n_edges);
    }
    // Kernels 2-3: scan chain
    scan_local_kernel<<<nb, 1024>>>(n_dst);
    scan_bsum_kernel<<<1, 32>>>(nb);
    // Kernel 4: scatter (2 warps/blk, 2 edges/lane) + precompute (5 warps/blk,
    // 2 rows/warp), striped; blocks cover max(edges/128, rows/10)
    {
        int b1 = (n_edges + 127) / 128;
        int b2 = (nmax + 9) / 10;
        int blocks = b1 > b2 ? b1 : b2;
        scatter_precompute_kernel<<<blocks, 224>>>(edge_idx, src_feat, dst_feat,
                                                   att_w, att_b,
                                                   n_edges, n_src, n_dst);
    }
    // Kernel 5: aggregate (R13 form)
    aggregate_kernel<<<(n_dst * 32 + 255) / 256, 256>>>(src_feat, out, n_dst);
}